// round 14
// baseline (speedup 1.0000x reference)
#include <cuda_runtime.h>
#include <cuda_bf16.h>
#include <stdint.h>

// ---------------------------------------------------------------------------
// GLCM layer, one kernel, vectorized tile load:
//   out[b, a*64+code, py, px] =
//     (1/1024) * sum_{t in 36x36 ext. window} wy(i)*wx(j) *
//                [ code(reflect(t)) == code ]
// code(s) = 8*gl(s) + gl(clamp(s + shift_a)),  gl = ceil(x/32)-1.
//
// Each CTA: one (batch, pool-cell, angle-group-of-4); angle groups own
// disjoint output channels. Tile covers x in [X0-4, X0+36) x y in
// [Y0-3, Y0+35): 38 rows x 40 cols, stored as CLAMPED gray levels, so
// neighbor reads never clamp. Interior-x CTAs (px 1..6) load the tile as
// 380 aligned float4 LDGs (<=1 per thread -> MLP_p1=1, no L1tex-queue
// contention); px 0/7 use a scalar clamped gather. Interior pool cells
// skip reflect math entirely (CTA-uniform).
// ---------------------------------------------------------------------------

#define H 256
#define W 256
#define NPIX (H * W)
#define NB 2
#define L2BINS 64
#define POOL 32
#define EXT 36            // 32 + 2*2 (box radius)
#define TROWS 38          // y: [Y0-3, Y0+35)
#define TCOLS 40          // x: [X0-4, X0+36)
#define NT 512
#define NW 8              // histogram copies (warp pairs share)
#define NBINS 256         // 4 angles x 64 codes per CTA

__device__ __forceinline__ int quant(float v) {
    // gl = ceil(v/32) - 1 == searchsorted_left(bins, v) - 1 ; exact
    return __float2int_ru(v * 0.03125f) - 1;
}

template<int O0, int O1, int O2, int O3, bool INTERIOR>
__device__ __forceinline__
void hist_loop(const int8_t* __restrict__ tile, int* __restrict__ whist,
               int tid, int Y0, int X0) {
    #pragma unroll
    for (int t = 0; t < 3; t++) {
        int pos = tid + t * NT;
        if (t == 2 && pos >= EXT * EXT) break;
        int i = pos / EXT;
        int j = pos - i * EXT;

        const int8_t* base;
        if (INTERIOR) {
            // ty = Y0-2+i -> row i+1 ; tx = X0-2+j -> col j+2
            base = &tile[(i + 1) * TCOLS + (j + 2)];
        } else {
            // reflect-pad mapping for the box-filter position
            int ty = Y0 - 2 + i; if (ty < 0) ty = -ty; else if (ty > H - 1) ty = 2 * (H - 1) - ty;
            int tx = X0 - 2 + j; if (tx < 0) tx = -tx; else if (tx > W - 1) tx = 2 * (W - 1) - tx;
            base = &tile[(ty - Y0 + 3) * TCOLS + (tx - X0 + 4)];
        }

        // 5 LDS with immediate offsets, issued before the weight math
        int g1 = base[0];
        int n0 = base[O0];
        int n1 = base[O1];
        int n2 = base[O2];
        int n3 = base[O3];

        // separable triangular weights 1,2,3,4,5,...,5,4,3,2,1
        int wgt = min(min(i + 1, EXT - i), 5) * min(min(j + 1, EXT - j), 5);

        int c8 = g1 << 3;
        int c0 = c8 + n0, c1 = c8 + n1, c2 = c8 + n2, c3 = c8 + n3;
        // guard matches reference one-hot: only codes in [0,64) are counted
        if ((unsigned)c0 < (unsigned)L2BINS) atomicAdd(&whist[c0], wgt);
        if ((unsigned)c1 < (unsigned)L2BINS) atomicAdd(&whist[L2BINS + c1], wgt);
        if ((unsigned)c2 < (unsigned)L2BINS) atomicAdd(&whist[2 * L2BINS + c2], wgt);
        if ((unsigned)c3 < (unsigned)L2BINS) atomicAdd(&whist[3 * L2BINS + c3], wgt);
    }
}

__global__ __launch_bounds__(NT, 4)
void glcm_kernel(const float* __restrict__ x, float* __restrict__ out) {
    const int px = blockIdx.x;            // 0..7
    const int py = blockIdx.y;            // 0..7
    const int b  = blockIdx.z >> 1;       // 0..1
    const int ag = blockIdx.z & 1;        // angle group: 0 -> angles 0-3, 1 -> 4-7
    const int X0 = px * POOL;
    const int Y0 = py * POOL;
    const int tid = threadIdx.x;

    __shared__ int8_t tile[TROWS * TCOLS];   // 1520 B
    __shared__ int    hist[NW][NBINS];       // 8 x 256 ints = 8 KB

    const float* xb = x + b * NPIX;
    const bool vecx = ((unsigned)(px - 1) < 6u);   // px 1..6: x-range in bounds

    if (vecx) {
        // ---- vectorized load: 380 float4s, <=1 per thread ----
        float4 v4;
        int r = 0, c4 = 0;
        if (tid < TROWS * (TCOLS / 4)) {
            r  = tid / (TCOLS / 4);
            c4 = tid - r * (TCOLS / 4);
            int gy = min(max(Y0 - 3 + r, 0), H - 1);
            v4 = *(const float4*)(xb + gy * W + (X0 - 4) + c4 * 4);
        }
        // zero histograms while the load is in flight (one int4 per thread)
        ((int4*)hist)[tid] = make_int4(0, 0, 0, 0);
        if (tid < TROWS * (TCOLS / 4)) {
            char4 q;
            q.x = (char)quant(v4.x);
            q.y = (char)quant(v4.y);
            q.z = (char)quant(v4.z);
            q.w = (char)quant(v4.w);
            *(char4*)&tile[r * TCOLS + c4 * 4] = q;
        }
    } else {
        // ---- scalar clamped gather (px 0 or 7): 1520 elems, 3 trips ----
        float v[3]; int rr[3], cc[3];
        #pragma unroll
        for (int k = 0; k < 3; k++) {
            int idx = tid + k * NT;
            rr[k] = idx / TCOLS; cc[k] = idx - rr[k] * TCOLS;
            if (idx < TROWS * TCOLS) {
                int gy = min(max(Y0 - 3 + rr[k], 0), H - 1);
                int gx = min(max(X0 - 4 + cc[k], 0), W - 1);
                v[k] = xb[gy * W + gx];
            }
        }
        ((int4*)hist)[tid] = make_int4(0, 0, 0, 0);
        #pragma unroll
        for (int k = 0; k < 3; k++) {
            int idx = tid + k * NT;
            if (idx < TROWS * TCOLS)
                tile[rr[k] * TCOLS + cc[k]] = (int8_t)quant(v[k]);
        }
    }
    __syncthreads();

    int* whist = hist[(tid >> 5) & (NW - 1)];   // warp pairs share a copy

    const bool interior = ((unsigned)(px - 1) < 6u) && ((unsigned)(py - 1) < 6u);
    // shifts: group 0 = (1,0)(1,-1)(0,-1)(-1,-1); group 1 = (-1,0)(-1,1)(0,1)(1,1)
    if (ag == 0) {
        if (interior) hist_loop< 1, -TCOLS + 1, -TCOLS, -TCOLS - 1, true >(tile, whist, tid, Y0, X0);
        else          hist_loop< 1, -TCOLS + 1, -TCOLS, -TCOLS - 1, false>(tile, whist, tid, Y0, X0);
    } else {
        if (interior) hist_loop<-1,  TCOLS - 1,  TCOLS,  TCOLS + 1, true >(tile, whist, tid, Y0, X0);
        else          hist_loop<-1,  TCOLS - 1,  TCOLS,  TCOLS + 1, false>(tile, whist, tid, Y0, X0);
    }
    __syncthreads();

    // reduce 8 histograms; write this CTA's disjoint output slice
    const float inv = 1.0f / (float)(POOL * POOL);
    if (tid < NBINS) {
        int s = 0;
        #pragma unroll
        for (int wp = 0; wp < NW; wp++) s += hist[wp][tid];
        int ch = ag * NBINS + tid;           // global channel in [0,512)
        out[((b * 512 + ch) * 8 + py) * 8 + px] = (float)s * inv;
    }
}

extern "C" void kernel_launch(void* const* d_in, const int* in_sizes, int n_in,
                              void* d_out, int out_size) {
    const float* x = (const float*)d_in[0];
    float* out = (float*)d_out;
    dim3 grid(8, 8, NB * 2);
    glcm_kernel<<<grid, NT>>>(x, out);
}